// round 1
// baseline (speedup 1.0000x reference)
#include <cuda_runtime.h>
#include <cstdint>
#include <math_constants.h>

// Problem constants
#define BATCH      64
#define SEQ        2048
#define H_DIM      1024
#define NSPLIT     8
#define ROWS_PER_CTA (SEQ / NSPLIT)          // 256
#define STAGE_ROWS 16
#define NSTAGES    (ROWS_PER_CTA / STAGE_ROWS) // 16
#define NBUF       3
#define STAGE_BYTES (STAGE_ROWS * H_DIM * 4)   // 65536
#define SMEM_BUF_BYTES (NBUF * STAGE_BYTES)    // 196608
#define SMEM_TOTAL (SMEM_BUF_BYTES + 128)

// Cross-kernel scratch (allocation-free: __device__ globals)
__device__ float g_num[BATCH * NSPLIT * H_DIM];   // per-split numerator (already exp-weighted)
__device__ float g_ml[BATCH * NSPLIT * 2];        // per-split (M, L)

// ---------------- PTX helpers ----------------
__device__ __forceinline__ uint32_t smem_u32(const void* p) {
    uint32_t a;
    asm("{ .reg .u64 t; cvta.to.shared.u64 t, %1; cvt.u32.u64 %0, t; }"
        : "=r"(a) : "l"(p));
    return a;
}

#define MBARRIER_INIT(addr, count) \
    asm volatile("mbarrier.init.shared.b64 [%0], %1;" \
                 :: "r"((uint32_t)(addr)), "r"((uint32_t)(count)) : "memory")

#define MBARRIER_EXPECT_TX(addr, bytes) \
    asm volatile("mbarrier.arrive.expect_tx.shared.b64 _, [%0], %1;" \
                 :: "r"((uint32_t)(addr)), "r"((uint32_t)(bytes)) : "memory")

#define MBARRIER_WAIT_PARITY(mbar_smem_addr, phase_parity) do { \
    uint32_t _mbar = (uint32_t)(mbar_smem_addr); \
    uint32_t _parity = (uint32_t)(phase_parity); \
    uint32_t _done; \
    asm volatile( \
        "{\n\t" \
        ".reg .pred p;\n\t" \
        "mbarrier.try_wait.parity.acquire.cta.shared::cta.b64 p, [%1], %2;\n\t" \
        "selp.b32 %0, 1, 0, p;\n\t" \
        "}" \
        : "=r"(_done) : "r"(_mbar), "r"(_parity) : "memory"); \
    if (!_done) { \
        asm volatile( \
            "{\n\t" \
            ".reg .pred P1;\n\t" \
            "WAIT_LOOP_%=:\n\t" \
            "mbarrier.try_wait.parity.acquire.cta.shared::cta.b64 P1, [%0], %1, 0x989680;\n\t" \
            "@P1 bra.uni WAIT_DONE_%=;\n\t" \
            "bra.uni WAIT_LOOP_%=;\n\t" \
            "WAIT_DONE_%=:\n\t" \
            "}" \
            :: "r"(_mbar), "r"(_parity) : "memory"); \
    } \
} while (0)

#define BULK_G2S(dst_smem, src_gmem, nbytes, mbar) \
    asm volatile("cp.async.bulk.shared::cluster.global.mbarrier::complete_tx::bytes " \
                 "[%0], [%1], %2, [%3];" \
                 :: "r"((uint32_t)(dst_smem)), "l"(src_gmem), \
                    "r"((uint32_t)(nbytes)), "r"((uint32_t)(mbar)) : "memory")

// ---------------- Pass 1: split-KV online softmax ----------------
// grid = BATCH*NSPLIT CTAs, 256 threads. Each CTA: 256 contiguous seq rows.
// Warp w handles rows {w*2, w*2+1} of each 16-row stage.
// Lane l owns columns {l*4 + i*128 + j : i in 0..7, j in 0..3}.
__global__ void __launch_bounds__(256, 1)
attn_pass1(const float* __restrict__ enc, const float* __restrict__ hn)
{
    extern __shared__ char smem[];
    const int tid = threadIdx.x;
    const int wid = tid >> 5;
    const int ln  = tid & 31;
    const int b   = blockIdx.x / NSPLIT;
    const int sp  = blockIdx.x % NSPLIT;

    const char* src_base =
        (const char*)(enc + ((size_t)b * SEQ + (size_t)sp * ROWS_PER_CTA) * H_DIM);

    const uint32_t sbase = smem_u32(smem);
    const uint32_t mbar0 = sbase + SMEM_BUF_BYTES;
    float* msh = (float*)(smem + SMEM_BUF_BYTES + 32);
    float* lsh = msh + 8;

    if (tid == 0) {
#pragma unroll
        for (int s = 0; s < NBUF; s++) MBARRIER_INIT(mbar0 + 8 * s, 1);
    }
    __syncthreads();

    // h_n[b] into registers, matching the per-lane column map
    float4 hreg[8];
    const float4* h4 = (const float4*)(hn + (size_t)b * H_DIM);
#pragma unroll
    for (int i = 0; i < 8; i++) hreg[i] = h4[i * 32 + ln];

    float m = -CUDART_INF_F;
    float l = 0.f;
    float4 acc[8];
#pragma unroll
    for (int i = 0; i < 8; i++) acc[i] = make_float4(0.f, 0.f, 0.f, 0.f);

    // Prologue: fill the pipeline
    if (tid == 0) {
#pragma unroll
        for (int s = 0; s < NBUF; s++) {
            MBARRIER_EXPECT_TX(mbar0 + 8 * s, STAGE_BYTES);
            BULK_G2S(sbase + s * STAGE_BYTES,
                     src_base + (size_t)s * STAGE_BYTES,
                     STAGE_BYTES, mbar0 + 8 * s);
        }
    }

    const float4* bufs = (const float4*)smem;

    for (int st = 0; st < NSTAGES; st++) {
        const int bsel = st % NBUF;
        const int par  = (st / NBUF) & 1;
        MBARRIER_WAIT_PARITY(mbar0 + 8 * bsel, par);
        const float4* tile = bufs + (size_t)bsel * (STAGE_ROWS * (H_DIM / 4));

#pragma unroll
        for (int rr = 0; rr < 2; rr++) {
            const float4* row = tile + (size_t)(wid * 2 + rr) * (H_DIM / 4);
            float4 v[8];
#pragma unroll
            for (int i = 0; i < 8; i++) v[i] = row[i * 32 + ln];   // 16B lane stride: conflict-free

            float d = 0.f;
#pragma unroll
            for (int i = 0; i < 8; i++) {
                d += v[i].x * hreg[i].x + v[i].y * hreg[i].y
                   + v[i].z * hreg[i].z + v[i].w * hreg[i].w;
            }
#pragma unroll
            for (int off = 16; off; off >>= 1)
                d += __shfl_xor_sync(0xffffffffu, d, off);

            const float mn = fmaxf(m, d);
            const float cf = __expf(m - mn);
            const float w  = __expf(d - mn);
            m = mn;
            l = l * cf + w;
#pragma unroll
            for (int i = 0; i < 8; i++) {
                acc[i].x = acc[i].x * cf + w * v[i].x;
                acc[i].y = acc[i].y * cf + w * v[i].y;
                acc[i].z = acc[i].z * cf + w * v[i].z;
                acc[i].w = acc[i].w * cf + w * v[i].w;
            }
        }
        __syncthreads();   // all warps done with buffer bsel
        if (tid == 0 && st + NBUF < NSTAGES) {
            MBARRIER_EXPECT_TX(mbar0 + 8 * bsel, STAGE_BYTES);
            BULK_G2S(sbase + bsel * STAGE_BYTES,
                     src_base + (size_t)(st + NBUF) * STAGE_BYTES,
                     STAGE_BYTES, mbar0 + 8 * bsel);
        }
    }

    // ---- Combine 8 warp partials within the CTA ----
    if (ln == 0) { msh[wid] = m; lsh[wid] = l; }
    __syncthreads();

    float M = msh[0];
#pragma unroll
    for (int w2 = 1; w2 < 8; w2++) M = fmaxf(M, msh[w2]);
    float L = 0.f;
#pragma unroll
    for (int w2 = 0; w2 < 8; w2++) L += lsh[w2] * __expf(msh[w2] - M);
    const float f = __expf(m - M);

    // Reuse stage buffer 0 as [8 warps][256 float4] combine scratch (32 KiB)
    float4* comb = (float4*)smem;
#pragma unroll
    for (int i = 0; i < 8; i++) {
        float4 t;
        t.x = acc[i].x * f; t.y = acc[i].y * f;
        t.z = acc[i].z * f; t.w = acc[i].w * f;
        comb[wid * 256 + i * 32 + ln] = t;
    }
    __syncthreads();

    float4 s = comb[tid];
#pragma unroll
    for (int w2 = 1; w2 < 8; w2++) {
        const float4 t = comb[w2 * 256 + tid];
        s.x += t.x; s.y += t.y; s.z += t.z; s.w += t.w;
    }
    ((float4*)g_num)[(size_t)(b * NSPLIT + sp) * 256 + tid] = s;
    if (tid == 0) {
        g_ml[(b * NSPLIT + sp) * 2 + 0] = M;
        g_ml[(b * NSPLIT + sp) * 2 + 1] = L;
    }
}

// ---------------- Pass 2: merge splits, write output ----------------
// grid = BATCH CTAs, 256 threads. out[b, 0, 0:1024] = h_n[b]; out[b, 0, 1024:2048] = context.
__global__ void __launch_bounds__(256)
attn_combine(const float* __restrict__ hn, float* __restrict__ out)
{
    const int b   = blockIdx.x;
    const int tid = threadIdx.x;

    float M = -CUDART_INF_F;
#pragma unroll
    for (int s = 0; s < NSPLIT; s++) M = fmaxf(M, g_ml[(b * NSPLIT + s) * 2]);
    float L = 0.f;
#pragma unroll
    for (int s = 0; s < NSPLIT; s++)
        L += g_ml[(b * NSPLIT + s) * 2 + 1] * __expf(g_ml[(b * NSPLIT + s) * 2] - M);

    float4 a = make_float4(0.f, 0.f, 0.f, 0.f);
    const float4* num4 = (const float4*)g_num;
#pragma unroll
    for (int s = 0; s < NSPLIT; s++) {
        const float fs = __expf(g_ml[(b * NSPLIT + s) * 2] - M);
        const float4 t = num4[(size_t)(b * NSPLIT + s) * 256 + tid];
        a.x += fs * t.x; a.y += fs * t.y; a.z += fs * t.z; a.w += fs * t.w;
    }
    const float inv = 1.0f / L;

    float4* out4 = (float4*)out;
    const float4* h4 = (const float4*)(hn + (size_t)b * H_DIM);
    out4[(size_t)b * 512 + tid] = h4[tid];
    float4 ctx;
    ctx.x = a.x * inv; ctx.y = a.y * inv; ctx.z = a.z * inv; ctx.w = a.w * inv;
    out4[(size_t)b * 512 + 256 + tid] = ctx;
}

// ---------------- Launch ----------------
extern "C" void kernel_launch(void* const* d_in, const int* in_sizes, int n_in,
                              void* d_out, int out_size)
{
    const float* enc = (const float*)d_in[0];   // (64, 2048, 1024) f32
    const float* hn  = (const float*)d_in[1];   // (64, 1024) f32
    float* out = (float*)d_out;                 // (64, 1, 2048) f32

    cudaFuncSetAttribute(attn_pass1,
                         cudaFuncAttributeMaxDynamicSharedMemorySize, SMEM_TOTAL);

    attn_pass1<<<BATCH * NSPLIT, 256, SMEM_TOTAL>>>(enc, hn);
    attn_combine<<<BATCH, 256>>>(hn, out);
}